// round 11
// baseline (speedup 1.0000x reference)
#include <cuda_runtime.h>
#include <cstdint>

// Problem constants
#define EE 130                     // 2*D + 2
#define HE 1040                    // H*E
#define NTOK 32768                 // B*N
#define TENSOR_ELEMS (NTOK * HE)

#define TT 32                      // tokens per tile
#define NTILES_T 1024              // tiles per type
#define THREADS 256
#define CTAS_PER_TYPE 74
#define GRID (4 * CTAS_PER_TYPE)   // 296 = 2 CTAs/SM * 148 SMs

#define MAT_STRIDE 4100            // 64*64 + 4 pad
#define WSM_FLOATS (4 * MAT_STRIDE)
#define XS_FLOATS (TT * 64)
#define SMEM_BYTES ((WSM_FLOATS + XS_FLOATS) * 4)   // 73,792 B -> 2 CTAs/SM

__device__ __forceinline__ double fma2(double a, double b, double c) {
    double d;
    asm("fma.rn.f32x2 %0, %1, %2, %3;" : "=d"(d) : "d"(a), "d"(b), "d"(c));
    return d;
}
__device__ __forceinline__ float pair_sum(double a) {
    return __int_as_float(__double2loint(a)) + __int_as_float(__double2hiint(a));
}

extern __shared__ float smem[];

// CTA types: 0=Q (M_q, x2), 1=K (M_k, x1), 2=V h0-3 (x1), 3=V h4-7 (x1)
__global__ __launch_bounds__(THREADS, 2)
void qkv_kernel(const float* __restrict__ x,
                const float* __restrict__ Mq,
                const float* __restrict__ Bq,
                const float* __restrict__ Mk,
                const float* __restrict__ Bk,
                const float* __restrict__ Mv,
                float* __restrict__ out)
{
    const int type = blockIdx.x & 3;
    const int cta  = blockIdx.x >> 2;       // 0..73 (same across the 4 types)
    const int tid  = threadIdx.x;
    const int warp = tid >> 5, lane = tid & 31;

    float* wsm = smem;
    float* xs  = smem + WSM_FLOATS;

    float* outQ = out;
    float* outK = out + (size_t)TENSOR_ELEMS;
    float* outV = out + (size_t)2 * TENSOR_ELEMS;

    // ---- Stage 4 weight matrices ONCE (float4 LDG -> swizzled float4 STS) ----
    const float* wsrc = (type == 0) ? Mq
                      : (type == 1) ? Mk
                      : (type == 2) ? Mv
                      :               (Mv + 4 * 4096);
    for (int idx = tid; idx < 4 * 1024; idx += THREADS) {
        int mat = idx >> 10;
        int r4  = idx & 1023;
        int i   = r4 >> 4;             // output row of M (= compute "col")
        int kp0 = (r4 & 15) * 2;       // first k-pair (even)
        float4 v = ((const float4*)(wsrc + mat * 4096))[r4];
        int s0 = (kp0 + 2 * (i & 7)) & 31;
        *(float4*)(wsm + mat * MAT_STRIDE + i * 64 + s0 * 2) = v;
    }

    // ---- Aux span decode: 32 spans per tile-group, one per warp ----
    // sp 0-7:   q head sp   : zeros [0,65) + scalar        (akind 0)
    // sp 8-15:  k head sp-8 : zeros [0,65) + scalar        (akind 0)
    // sp 16-19: q head 4+.. : zeros [66,130)               (akind 1)
    // sp 20-23: k head 4+.. : zeros [66,130)               (akind 1)
    // sp 24-31: v head sp-24: zeros [0,65) + {129}         (akind 2)
    const int sp = type * 8 + warp;
    float* auxT; int ah, akind, spos = 0, ssrc = 0; float abv = 0.f;
    if (sp < 8)       { auxT = outQ; ah = sp;           akind = 0;
                        spos = (ah < 4) ? 129 : 65; ssrc = 129; abv = Bq[ah]; }
    else if (sp < 16) { auxT = outK; ah = sp - 8;       akind = 0;
                        spos = (ah < 4) ? 129 : 65; ssrc = (ah < 4) ? 129 : 64; abv = Bk[ah]; }
    else if (sp < 20) { auxT = outQ; ah = 4 + (sp - 16); akind = 1; }
    else if (sp < 24) { auxT = outK; ah = 4 + (sp - 20); akind = 1; }
    else              { auxT = outV; ah = sp - 24;       akind = 2; }

    // ---- Compute-lane decomposition ----
    const int tokG   = warp >> 1;
    const int half   = warp & 1;
    const int mi     = lane >> 3;
    const int colSub = lane & 7;
    const int myTok0 = tokG * 8;
    const int xoff   = (type == 0) ? 65 : 0;

    float* T;
    int h;
    if (type == 0)      { T = outQ; h = mi; }
    else if (type == 1) { T = outK; h = mi; }
    else                { T = outV; h = ((type == 2) ? 0 : 4) + mi; }

    const float* wrow0 = wsm + mi * MAT_STRIDE + (colSub + 32 * half) * 64;
    const float* xbase = xs + myTok0 * 64;
    const float2 z2 = make_float2(0.f, 0.f);

    // ---- Persistent tile loop (the 4 type-CTAs with same `cta` are adjacent
    //      block IDs -> adjacent SMs -> same-row writes stay L2-resident) ----
    for (int tile = cta; tile < NTILES_T; tile += CTAS_PER_TYPE) {
        const int tok0 = tile * TT;
        __syncthreads();   // xs free (prev compute done); also orders weight staging

        // stage x slice (Q: x2 = x[65:129], else x1)
        for (int idx = tid; idx < TT * 64; idx += THREADS) {
            int t = idx >> 6, e = idx & 63;
            xs[idx] = x[(size_t)(tok0 + t) * EE + xoff + e];
        }

        // tile-local aux: this warp's span for all 32 tokens of the tile
        #pragma unroll 4
        for (int t = 0; t < TT; ++t) {
            float* rowh = auxT + (size_t)(tok0 + t) * HE + ah * 130;
            if (akind == 1) {
                *(float2*)(rowh + 66 + 2 * lane) = z2;
            } else {
                *(float2*)(rowh + 2 * lane) = z2;
                if (lane == 0) rowh[64] = 0.f;
                if (akind == 0) {
                    if (lane == 1) rowh[spos] = x[(size_t)(tok0 + t) * EE + ssrc] * abv;
                } else {
                    if (lane == 1) rowh[129] = 0.f;
                }
            }
        }

        __syncthreads();

        // ---- pipelined compute: 16 iters of 2 k-pairs ----
        double acc[8][4];
        #pragma unroll
        for (int i = 0; i < 8; ++i)
            #pragma unroll
            for (int j = 0; j < 4; ++j) acc[i][j] = 0.0;

        double2 xp[8], wp[4];
        #pragma unroll
        for (int i = 0; i < 8; ++i) xp[i] = *(const double2*)(xbase + i * 64);
        {
            const int s = (2 * colSub) & 31;
            #pragma unroll
            for (int j = 0; j < 4; ++j) wp[j] = *(const double2*)(wrow0 + j * 512 + s * 2);
        }

        #pragma unroll 3
        for (int it = 0; it < 15; ++it) {
            #pragma unroll
            for (int i = 0; i < 8; ++i) {
                #pragma unroll
                for (int j = 0; j < 4; ++j) {
                    acc[i][j] = fma2(xp[i].x, wp[j].x, acc[i][j]);
                    acc[i][j] = fma2(xp[i].y, wp[j].y, acc[i][j]);
                }
                xp[i] = *(const double2*)(xbase + i * 64 + 4 * (it + 1));  // prefetch
            }
            const int s = (2 * (it + 1) + 2 * colSub) & 31;
            #pragma unroll
            for (int j = 0; j < 4; ++j)
                wp[j] = *(const double2*)(wrow0 + j * 512 + s * 2);        // prefetch
        }
        #pragma unroll
        for (int i = 0; i < 8; ++i)
            #pragma unroll
            for (int j = 0; j < 4; ++j) {
                acc[i][j] = fma2(xp[i].x, wp[j].x, acc[i][j]);
                acc[i][j] = fma2(xp[i].y, wp[j].y, acc[i][j]);
            }

        // ---- epilogue: computed outputs ----
        #pragma unroll
        for (int i = 0; i < 8; ++i) {
            float* o = T + (size_t)(tok0 + myTok0 + i) * HE + h * 130 + 65 + 32 * half + colSub;
            #pragma unroll
            for (int j = 0; j < 4; ++j)
                o[8 * j] = pair_sum(acc[i][j]);
        }
    }
}

extern "C" void kernel_launch(void* const* d_in, const int* in_sizes, int n_in,
                              void* d_out, int out_size) {
    const float* x  = (const float*)d_in[0];
    const float* Mq = (const float*)d_in[1];
    const float* Bq = (const float*)d_in[2];
    const float* Mk = (const float*)d_in[3];
    const float* Bk = (const float*)d_in[4];
    const float* Mv = (const float*)d_in[5];
    float* out = (float*)d_out;

    cudaFuncSetAttribute(qkv_kernel, cudaFuncAttributeMaxDynamicSharedMemorySize, SMEM_BYTES);
    qkv_kernel<<<GRID, THREADS, SMEM_BYTES>>>(x, Mq, Bq, Mk, Bk, Mv, out);
}

// round 15
// speedup vs baseline: 1.6704x; 1.6704x over previous
#include <cuda_runtime.h>
#include <cstdint>

// Problem constants
#define EE 130                     // 2*D + 2
#define HE 1040                    // H*E
#define NTOK 32768                 // B*N
#define TENSOR_ELEMS (NTOK * HE)

#define TT 32                      // tokens per CTA tile
#define NTILES (NTOK / TT)         // 1024
#define THREADS 256

#define MAT_STRIDE 4100            // 64*64 + 4 pad
#define WSM_FLOATS (4 * MAT_STRIDE)
#define XS_FLOATS (TT * 64)
#define SMEM_BYTES ((WSM_FLOATS + XS_FLOATS) * 4)   // 73,792 B -> 2 CTAs/SM

__device__ __forceinline__ double fma2(double a, double b, double c) {
    double d;
    asm("fma.rn.f32x2 %0, %1, %2, %3;" : "=d"(d) : "d"(a), "d"(b), "d"(c));
    return d;
}
__device__ __forceinline__ float pair_sum(double a) {
    return __int_as_float(__double2loint(a)) + __int_as_float(__double2hiint(a));
}

extern __shared__ float smem[];

// CTA types: 0=Q (M_q, x2), 1=K (M_k, x1), 2=V h0-3 (x1), 3=V h4-7 (x1)
__global__ __launch_bounds__(THREADS, 2)
void qkv_kernel(const float* __restrict__ x,
                const float* __restrict__ Mq,
                const float* __restrict__ Bq,
                const float* __restrict__ Mk,
                const float* __restrict__ Bk,
                const float* __restrict__ Mv,
                float* __restrict__ out)
{
    const int type = blockIdx.x & 3;
    const int tile = blockIdx.x >> 2;
    const int tok0 = tile * TT;
    const int tid  = threadIdx.x;

    float* wsm = smem;
    float* xs  = smem + WSM_FLOATS;

    float* outQ = out;
    float* outK = out + (size_t)TENSOR_ELEMS;
    float* outV = out + (size_t)2 * TENSOR_ELEMS;

    // ---- Stage 4 weight matrices (float4 LDG -> swizzled float4 STS) ----
    const float* wsrc = (type == 0) ? Mq
                      : (type == 1) ? Mk
                      : (type == 2) ? Mv
                      :               (Mv + 4 * 4096);
    for (int idx = tid; idx < 4 * 1024; idx += THREADS) {
        int mat = idx >> 10;
        int r4  = idx & 1023;
        int i   = r4 >> 4;             // output row of M (= compute "col")
        int kp0 = (r4 & 15) * 2;       // first k-pair (even)
        float4 v = ((const float4*)(wsrc + mat * 4096))[r4];
        int s0 = (kp0 + 2 * (i & 7)) & 31;
        *(float4*)(wsm + mat * MAT_STRIDE + i * 64 + s0 * 2) = v;
    }

    // ---- Stage x slice for this CTA type (Q uses x2 = x[65:129], else x1) ----
    const int xoff = (type == 0) ? 65 : 0;
    for (int idx = tid; idx < TT * 64; idx += THREADS) {
        int t = idx >> 6, e = idx & 63;
        xs[idx] = x[(size_t)(tok0 + t) * EE + xoff + e];
    }

    // ---- Structural zeros + scalar outputs (disjoint from computed addrs) ----
    const int warp = tid >> 5, lane = tid & 31;
    if (type < 2) {
        float* T = type ? outK : outQ;
        for (int r = warp; r < 256; r += 8) {          // zeros [0,65), all heads
            int t = r >> 3, h = r & 7;
            float* base = T + (size_t)(tok0 + t) * HE + h * 130;
            base[lane] = 0.f; base[lane + 32] = 0.f;
            if (lane == 0) base[64] = 0.f;
        }
        for (int r = warp; r < 128; r += 8) {          // heads 4-7: zeros [66,130)
            int t = r >> 2, h = 4 + (r & 3);
            float* base = T + (size_t)(tok0 + t) * HE + h * 130 + 66;
            base[lane] = 0.f; base[lane + 32] = 0.f;
        }
        for (int r = tid; r < 256; r += THREADS) {     // scalar outputs
            int t = r >> 3, h = r & 7;
            const float* xr = x + (size_t)(tok0 + t) * EE;
            float s, bv; int pos;
            if (type == 0) { bv = Bq[h]; s = xr[129]; pos = (h < 4) ? 129 : 65; }
            else {
                bv = Bk[h];
                if (h < 4) { s = xr[129]; pos = 129; }
                else       { s = xr[64];  pos = 65;  }
            }
            T[(size_t)(tok0 + t) * HE + h * 130 + pos] = s * bv;
        }
    } else {
        int h0 = (type == 2) ? 0 : 4;                  // v: zeros [0,65) and {129}
        for (int r = warp; r < 128; r += 8) {
            int t = r >> 2, h = h0 + (r & 3);
            float* base = outV + (size_t)(tok0 + t) * HE + h * 130;
            base[lane] = 0.f; base[lane + 32] = 0.f;
            if (lane == 0) { base[64] = 0.f; base[129] = 0.f; }
        }
    }

    __syncthreads();

    // ---- Compute: per-thread 8 tokens x 4 cols; 2 k-pairs per iteration ----
    const int tokG   = warp >> 1;
    const int half   = warp & 1;
    const int mi     = lane >> 3;
    const int colSub = lane & 7;
    const int myTok0 = tokG * 8;

    const float* wrow0 = wsm + mi * MAT_STRIDE + (colSub + 32 * half) * 64;
    const float* xbase = xs + myTok0 * 64;

    double acc[8][4];
    #pragma unroll
    for (int i = 0; i < 8; ++i)
        #pragma unroll
        for (int j = 0; j < 4; ++j) acc[i][j] = 0.0;

    // Double-buffered w operands: wp for iter `it` loaded one FULL iteration
    // (~128 fma-pipe cyc) before first use; x operands rotate depth-2
    // (~32 cyc gap > 29-cyc LDS latency).
    double2 wpA[4], wpB[4];
    {
        const int s0 = (2 * colSub) & 31;
        #pragma unroll
        for (int j = 0; j < 4; ++j)
            wpA[j] = *(const double2*)(wrow0 + j * 512 + s0 * 2);
    }

    #pragma unroll 4
    for (int it = 0; it < 16; ++it) {
        double2* cur = (it & 1) ? wpB : wpA;   // static per unrolled body
        double2* nxt = (it & 1) ? wpA : wpB;
        if (it < 15) {                          // prefetch w for it+1 at TOP
            const int sn = (2 * (it + 1) + 2 * colSub) & 31;
            #pragma unroll
            for (int j = 0; j < 4; ++j)
                nxt[j] = *(const double2*)(wrow0 + j * 512 + sn * 2);
        }

        double2 xa = *(const double2*)(xbase + 0 * 64 + 4 * it);
        double2 xb = *(const double2*)(xbase + 1 * 64 + 4 * it);
        #pragma unroll
        for (int i = 0; i < 8; ++i) {
            double2 xn;
            if (i < 6) xn = *(const double2*)(xbase + (i + 2) * 64 + 4 * it);
            #pragma unroll
            for (int j = 0; j < 4; ++j) {
                acc[i][j] = fma2(xa.x, cur[j].x, acc[i][j]);
                acc[i][j] = fma2(xa.y, cur[j].y, acc[i][j]);
            }
            xa = xb; xb = xn;
        }
    }

    // ---- Epilogue: computed outputs ----
    float* T;
    int h;
    if (type == 0)      { T = outQ; h = mi; }
    else if (type == 1) { T = outK; h = mi; }
    else                { T = outV; h = ((type == 2) ? 0 : 4) + mi; }

    #pragma unroll
    for (int i = 0; i < 8; ++i) {
        float* o = T + (size_t)(tok0 + myTok0 + i) * HE + h * 130 + 65 + 32 * half + colSub;
        #pragma unroll
        for (int j = 0; j < 4; ++j)
            o[8 * j] = pair_sum(acc[i][j]);
    }
}

extern "C" void kernel_launch(void* const* d_in, const int* in_sizes, int n_in,
                              void* d_out, int out_size) {
    const float* x  = (const float*)d_in[0];
    const float* Mq = (const float*)d_in[1];
    const float* Bq = (const float*)d_in[2];
    const float* Mk = (const float*)d_in[3];
    const float* Bk = (const float*)d_in[4];
    const float* Mv = (const float*)d_in[5];
    float* out = (float*)d_out;

    cudaFuncSetAttribute(qkv_kernel, cudaFuncAttributeMaxDynamicSharedMemorySize, SMEM_BYTES);
    qkv_kernel<<<4 * NTILES, THREADS, SMEM_BYTES>>>(x, Mq, Bq, Mk, Bk, Mv, out);
}